// round 2
// baseline (speedup 1.0000x reference)
#include <cuda_runtime.h>

// CoupledCLEFOModel: y = ((1+eps)I - Gamma - diag(Lambda@x))^{-1} (Ups + B@x + Theta@z)
// Jacobi splitting: A = D_s - Gamma, D_s = diag(1+eps - lam_i).
//   y_{k+1} = D^{-1} rhs + D^{-1} (Gamma y_k),  contraction rho <= ~0.2 -> 9 iters ~1e-7.
// One thread per sample; parameter matrices transposed in SMEM for broadcast LDS.

#define NDEP  32
#define NIND  64
#define NINT  16
#define TPB   128
#define NITER 9
#define REGC  1e-7f

__global__ __launch_bounds__(TPB, 2)
void clefo_kernel(const float* __restrict__ X,
                  const float* __restrict__ Z,
                  const float* __restrict__ Ups,
                  const float* __restrict__ Bm,
                  const float* __restrict__ Th,
                  const float* __restrict__ Gm,
                  const float* __restrict__ Lm,
                  float* __restrict__ out,
                  int batch)
{
    __shared__ float sBt[NIND][NDEP];   // sBt[j][i] = B[i][j]
    __shared__ float sLt[NIND][NDEP];   // sLt[j][i] = Lambda[i][j]
    __shared__ float sTt[NINT][NDEP];   // sTt[k][i] = Theta[i][k]
    __shared__ float sGt[NDEP][NDEP];   // sGt[j][i] = Gamma[i][j]
    __shared__ float sU[NDEP];

    const int tid = threadIdx.x;

    for (int idx = tid; idx < NDEP * NIND; idx += TPB) {
        int i = idx / NIND, j = idx % NIND;
        sBt[j][i] = Bm[idx];
        sLt[j][i] = Lm[idx];
    }
    for (int idx = tid; idx < NDEP * NINT; idx += TPB) {
        int i = idx / NINT, k = idx % NINT;
        sTt[k][i] = Th[idx];
    }
    for (int idx = tid; idx < NDEP * NDEP; idx += TPB) {
        int i = idx / NDEP, j = idx % NDEP;
        sGt[j][i] = Gm[idx];
    }
    if (tid < NDEP) sU[tid] = Ups[tid];
    __syncthreads();

    const int s = blockIdx.x * TPB + tid;
    if (s >= batch) return;

    float rhs[NDEP], lam[NDEP];
#pragma unroll
    for (int i = 0; i < NDEP; i++) { rhs[i] = sU[i]; lam[i] = 0.0f; }

    // ---- Phase 1: rhs += B@x, lam = Lambda@x  (x streamed as float4)
    const float4* X4 = reinterpret_cast<const float4*>(X + (size_t)s * NIND);
#pragma unroll 4
    for (int c = 0; c < NIND / 4; c++) {
        float4 xv = X4[c];
        {
            float xj = xv.x; int j = c * 4 + 0;
#pragma unroll
            for (int i = 0; i < NDEP; i++) { rhs[i] += sBt[j][i] * xj; lam[i] += sLt[j][i] * xj; }
        }
        {
            float xj = xv.y; int j = c * 4 + 1;
#pragma unroll
            for (int i = 0; i < NDEP; i++) { rhs[i] += sBt[j][i] * xj; lam[i] += sLt[j][i] * xj; }
        }
        {
            float xj = xv.z; int j = c * 4 + 2;
#pragma unroll
            for (int i = 0; i < NDEP; i++) { rhs[i] += sBt[j][i] * xj; lam[i] += sLt[j][i] * xj; }
        }
        {
            float xj = xv.w; int j = c * 4 + 3;
#pragma unroll
            for (int i = 0; i < NDEP; i++) { rhs[i] += sBt[j][i] * xj; lam[i] += sLt[j][i] * xj; }
        }
    }

    // ---- rhs += Theta@z
    const float4* Z4 = reinterpret_cast<const float4*>(Z + (size_t)s * NINT);
#pragma unroll
    for (int c = 0; c < NINT / 4; c++) {
        float4 zv = Z4[c];
        {
            float zk = zv.x; int k = c * 4 + 0;
#pragma unroll
            for (int i = 0; i < NDEP; i++) rhs[i] += sTt[k][i] * zk;
        }
        {
            float zk = zv.y; int k = c * 4 + 1;
#pragma unroll
            for (int i = 0; i < NDEP; i++) rhs[i] += sTt[k][i] * zk;
        }
        {
            float zk = zv.z; int k = c * 4 + 2;
#pragma unroll
            for (int i = 0; i < NDEP; i++) rhs[i] += sTt[k][i] * zk;
        }
        {
            float zk = zv.w; int k = c * 4 + 3;
#pragma unroll
            for (int i = 0; i < NDEP; i++) rhs[i] += sTt[k][i] * zk;
        }
    }

    // ---- Phase 2: dinv = 1/(1+eps - lam); rhs <- D^{-1} rhs; y0 = rhs
    float dinv[NDEP], y[NDEP];
#pragma unroll
    for (int i = 0; i < NDEP; i++) {
        float d = (1.0f + REGC) - lam[i];
        dinv[i] = 1.0f / d;
        rhs[i] *= dinv[i];
        y[i] = rhs[i];
    }

    // ---- Phase 3: Jacobi iterations  y = rhs + dinv .* (Gamma @ y)  (loop kept rolled)
    for (int it = 0; it < NITER; it++) {
        float acc[NDEP];
#pragma unroll
        for (int i = 0; i < NDEP; i++) acc[i] = 0.0f;
#pragma unroll
        for (int j = 0; j < NDEP; j++) {
            float yj = y[j];
#pragma unroll
            for (int i = 0; i < NDEP; i++) acc[i] += sGt[j][i] * yj;
        }
#pragma unroll
        for (int i = 0; i < NDEP; i++) y[i] = fmaf(dinv[i], acc[i], rhs[i]);
    }

    // ---- Write out
    float4* O4 = reinterpret_cast<float4*>(out + (size_t)s * NDEP);
#pragma unroll
    for (int c = 0; c < NDEP / 4; c++) {
        O4[c] = make_float4(y[4 * c + 0], y[4 * c + 1], y[4 * c + 2], y[4 * c + 3]);
    }
}

extern "C" void kernel_launch(void* const* d_in, const int* in_sizes, int n_in,
                              void* d_out, int out_size)
{
    const float* X   = (const float*)d_in[0];  // [batch, 64]
    const float* Z   = (const float*)d_in[1];  // [batch, 16]
    const float* Ups = (const float*)d_in[2];  // [32, 1]
    const float* Bm  = (const float*)d_in[3];  // [32, 64]
    const float* Th  = (const float*)d_in[4];  // [32, 16]
    const float* Gm  = (const float*)d_in[5];  // [32, 32]
    const float* Lm  = (const float*)d_in[6];  // [32, 64]
    float* out = (float*)d_out;

    int batch = in_sizes[0] / NIND;
    int nblocks = (batch + TPB - 1) / TPB;
    clefo_kernel<<<nblocks, TPB>>>(X, Z, Ups, Bm, Th, Gm, Lm, out, batch);
}